// round 1
// baseline (speedup 1.0000x reference)
#include <cuda_runtime.h>
#include <math.h>

#define N_NODES 10000
#define E_EDGES 160000
#define DCH 512
#define C_HEAD 256
#define HEADS 2
#define TDIM 128
#define MDIM 256
#define FDIM 384   // TDIM + MDIM

// ---------------- scratch (device globals: no cudaMalloc allowed) ----------------
__device__ float g_q[N_NODES * DCH];
__device__ float g_k[N_NODES * DCH];
__device__ float g_v[N_NODES * DCH];
__device__ float g_p[N_NODES * HEADS * FDIM];      // p[n][h][f] = sum_c q[n,h,c]*We[f,h*C+c]
__device__ float g_WeT[HEADS * C_HEAD * FDIM];     // WeT[h][c][f] = We[f][h*C+c]
__device__ float g_alpha[E_EDGES * HEADS];
__device__ float g_G[N_NODES * HEADS * FDIM];      // G[n][h][f] = sum_{e->n} alpha*ea[f]
__device__ int   g_deg[N_NODES];
__device__ int   g_cur[N_NODES];
__device__ int   g_off[N_NODES + 1];
__device__ int   g_perm[E_EDGES];

// ---------------- generic fp32 GEMM: C[M,N] = A[M,K](lda) * B[K,N](ldb) (+bias)(+acc) ----
// 64x64 tile, BK=16, 256 threads, 4x4 microtile. N,K multiples assumed (N%64==0, K%16==0).
__global__ void __launch_bounds__(256) gemm64(
    const float* __restrict__ A, int lda,
    const float* __restrict__ B, int ldb,
    float* __restrict__ C, int ldc,
    const float* __restrict__ bias,
    int M, int Ncols, int K, int acc)
{
    __shared__ float As[16][64];
    __shared__ float Bs[16][64];

    int tid = threadIdx.x;
    int bm = blockIdx.y * 64, bn = blockIdx.x * 64;
    int tx = tid & 15, ty = tid >> 4;

    int a_m = tid & 63;           // row within tile
    int a_k = (tid >> 6) * 4;     // k offset (0,4,8,12)
    int b_k = tid >> 4;           // 0..15
    int b_n = (tid & 15) * 4;

    bool arow = (bm + a_m) < M;
    const float* Ap = A + (size_t)(bm + a_m) * lda + a_k;
    const float* Bp = B + (size_t)b_k * ldb + bn + b_n;

    float accr[4][4];
#pragma unroll
    for (int i = 0; i < 4; i++)
#pragma unroll
        for (int j = 0; j < 4; j++) accr[i][j] = 0.f;

    for (int k0 = 0; k0 < K; k0 += 16) {
        float4 av = arow ? *(const float4*)(Ap + k0) : make_float4(0.f, 0.f, 0.f, 0.f);
        As[a_k + 0][a_m] = av.x;
        As[a_k + 1][a_m] = av.y;
        As[a_k + 2][a_m] = av.z;
        As[a_k + 3][a_m] = av.w;
        float4 bv = *(const float4*)(Bp + (size_t)k0 * ldb);
        *(float4*)&Bs[b_k][b_n] = bv;
        __syncthreads();
#pragma unroll
        for (int kk = 0; kk < 16; kk++) {
            float4 a4 = *(const float4*)&As[kk][ty * 4];
            float4 b4 = *(const float4*)&Bs[kk][tx * 4];
            float ar[4] = {a4.x, a4.y, a4.z, a4.w};
            float br[4] = {b4.x, b4.y, b4.z, b4.w};
#pragma unroll
            for (int i = 0; i < 4; i++)
#pragma unroll
                for (int j = 0; j < 4; j++) accr[i][j] += ar[i] * br[j];
        }
        __syncthreads();
    }

#pragma unroll
    for (int i = 0; i < 4; i++) {
        int row = bm + ty * 4 + i;
        if (row < M) {
#pragma unroll
            for (int j = 0; j < 4; j++) {
                int col = bn + tx * 4 + j;
                float v = accr[i][j];
                if (bias) v += bias[col];
                float* cp = C + (size_t)row * ldc + col;
                if (acc) *cp += v; else *cp = v;
            }
        }
    }
}

// ---------------- CSR build ----------------
__global__ void zero_deg_kernel() {
    int i = blockIdx.x * 256 + threadIdx.x;
    if (i < N_NODES) g_deg[i] = 0;
}

__global__ void count_deg_kernel(const int* __restrict__ ei) {
    int i = blockIdx.x * 256 + threadIdx.x;
    if (i < E_EDGES) atomicAdd(&g_deg[ei[E_EDGES + i]], 1);
}

__global__ void __launch_bounds__(1024) scan_kernel() {
    __shared__ int part[1024];
    int tid = threadIdx.x;
    int base = tid * 10;
    int local[10];
    int s = 0;
#pragma unroll
    for (int j = 0; j < 10; j++) {
        int idx = base + j;
        int d = (idx < N_NODES) ? g_deg[idx] : 0;
        local[j] = d;
        s += d;
    }
    part[tid] = s;
    __syncthreads();
    for (int off = 1; off < 1024; off <<= 1) {
        int v = part[tid];
        int add = (tid >= off) ? part[tid - off] : 0;
        __syncthreads();
        part[tid] = v + add;
        __syncthreads();
    }
    int run = (tid > 0) ? part[tid - 1] : 0;
#pragma unroll
    for (int j = 0; j < 10; j++) {
        int idx = base + j;
        if (idx < N_NODES) {
            g_off[idx] = run;
            run += local[j];
            g_cur[idx] = 0;
        }
    }
    if (tid == 1023) g_off[N_NODES] = part[1023];
}

__global__ void scatter_perm_kernel(const int* __restrict__ ei) {
    int i = blockIdx.x * 256 + threadIdx.x;
    if (i < E_EDGES) {
        int d = ei[E_EDGES + i];
        int p = g_off[d] + atomicAdd(&g_cur[d], 1);
        g_perm[p] = i;
    }
}

// ---------------- We transpose (per head): WeT[h][c][f] = We[f][h*C+c] ----------------
__global__ void transpose_we_kernel(const float* __restrict__ We) {
    int i = blockIdx.x * 256 + threadIdx.x;
    if (i < HEADS * C_HEAD * FDIM) {
        int h = i / (C_HEAD * FDIM);
        int r = i % (C_HEAD * FDIM);
        int c = r / FDIM;
        int f = r % FDIM;
        g_WeT[i] = We[(size_t)f * DCH + h * C_HEAD + c];
    }
}

// ---------------- per-edge attention logits (warp per edge) ----------------
// alpha[e,h] = ( q[dst]_h . k[src]_h  +  ea[e] . p[dst]_h ) / 16
__global__ void __launch_bounds__(256) edge_alpha_kernel(
    const int* __restrict__ ei, const float* __restrict__ tfeat,
    const float* __restrict__ msg)
{
    int w = (blockIdx.x * 256 + threadIdx.x) >> 5;
    int lane = threadIdx.x & 31;
    if (w >= E_EDGES) return;
    int src = ei[w];
    int dst = ei[E_EDGES + w];
    const float* qr = g_q + (size_t)dst * DCH;
    const float* kr = g_k + (size_t)src * DCH;
    const float* pr = g_p + (size_t)dst * (HEADS * FDIM);
    float a0 = 0.f, a1 = 0.f;
    for (int c = lane; c < C_HEAD; c += 32) {
        a0 += qr[c] * kr[c];
        a1 += qr[c + C_HEAD] * kr[c + C_HEAD];
    }
    const float* tr = tfeat + (size_t)w * TDIM;
    for (int f = lane; f < TDIM; f += 32) {
        float e = tr[f];
        a0 += e * pr[f];
        a1 += e * pr[FDIM + f];
    }
    const float* mr = msg + (size_t)w * MDIM;
    for (int f = lane; f < MDIM; f += 32) {
        float e = mr[f];
        a0 += e * pr[TDIM + f];
        a1 += e * pr[FDIM + TDIM + f];
    }
#pragma unroll
    for (int o = 16; o; o >>= 1) {
        a0 += __shfl_xor_sync(0xffffffffu, a0, o);
        a1 += __shfl_xor_sync(0xffffffffu, a1, o);
    }
    if (lane == 0) {
        g_alpha[2 * w + 0] = a0 * 0.0625f;   // / sqrt(256)
        g_alpha[2 * w + 1] = a1 * 0.0625f;
    }
}

// ---------------- per-node softmax + aggregation (block of 128 per node) ----------------
// out[n] += sum_e w * v[src]          (channels: thread owns 4 consecutive)
// G[n][h][f] = sum_e w_h * ea[e][f]   (thread owns 6 consecutive of the 768)
__global__ void __launch_bounds__(128) aggregate_kernel(
    const int* __restrict__ ei, const float* __restrict__ tfeat,
    const float* __restrict__ msg, float* __restrict__ out)
{
    int n = blockIdx.x;
    int tid = threadIdx.x;
    int beg = g_off[n], end = g_off[n + 1];
    int deg = end - beg;

    if (deg == 0) {
        // must clear G every replay (graph capture reuses buffers)
#pragma unroll
        for (int l = 0; l < 6; l++)
            g_G[(size_t)n * (HEADS * FDIM) + tid * 6 + l] = 0.f;
        return;
    }

    __shared__ float red0[128], red1[128];

    // segment max
    float m0 = -1e30f, m1 = -1e30f;
    for (int i = tid; i < deg; i += 128) {
        int e = g_perm[beg + i];
        m0 = fmaxf(m0, g_alpha[2 * e + 0]);
        m1 = fmaxf(m1, g_alpha[2 * e + 1]);
    }
    red0[tid] = m0; red1[tid] = m1;
    __syncthreads();
    for (int s = 64; s; s >>= 1) {
        if (tid < s) {
            red0[tid] = fmaxf(red0[tid], red0[tid + s]);
            red1[tid] = fmaxf(red1[tid], red1[tid + s]);
        }
        __syncthreads();
    }
    float amax0 = red0[0], amax1 = red1[0];
    __syncthreads();

    // segment sum of exp
    float d0 = 0.f, d1 = 0.f;
    for (int i = tid; i < deg; i += 128) {
        int e = g_perm[beg + i];
        d0 += expf(g_alpha[2 * e + 0] - amax0);
        d1 += expf(g_alpha[2 * e + 1] - amax1);
    }
    red0[tid] = d0; red1[tid] = d1;
    __syncthreads();
    for (int s = 64; s; s >>= 1) {
        if (tid < s) {
            red0[tid] += red0[tid + s];
            red1[tid] += red1[tid + s];
        }
        __syncthreads();
    }
    float inv0 = 1.f / (red0[0] + 1e-16f);
    float inv1 = 1.f / (red1[0] + 1e-16f);
    __syncthreads();

    __shared__ int s_eid[128];
    __shared__ int s_src[128];
    __shared__ float s_w0[128], s_w1[128];

    float acc0 = 0.f, acc1 = 0.f, acc2 = 0.f, acc3 = 0.f;
    float gacc[6] = {0.f, 0.f, 0.f, 0.f, 0.f, 0.f};

    // precompute this thread's G indices
    int gf[6]; bool gh1[6];
#pragma unroll
    for (int l = 0; l < 6; l++) {
        int idx = tid * 6 + l;
        gh1[l] = (idx >= FDIM);
        gf[l] = gh1[l] ? idx - FDIM : idx;
    }

    for (int base = 0; base < deg; base += 128) {
        int cnt = min(128, deg - base);
        if (tid < cnt) {
            int e = g_perm[beg + base + tid];
            s_eid[tid] = e;
            s_src[tid] = ei[e];
            s_w0[tid] = expf(g_alpha[2 * e + 0] - amax0) * inv0;
            s_w1[tid] = expf(g_alpha[2 * e + 1] - amax1) * inv1;
        }
        __syncthreads();
        for (int j = 0; j < cnt; j++) {
            int e = s_eid[j];
            int src = s_src[j];
            float w0 = s_w0[j], w1 = s_w1[j];
            float wv = (tid < 64) ? w0 : w1;   // channels tid*4..+3 stay in one head
            float4 vv = *(const float4*)(g_v + (size_t)src * DCH + tid * 4);
            acc0 += wv * vv.x; acc1 += wv * vv.y; acc2 += wv * vv.z; acc3 += wv * vv.w;
            const float* tr = tfeat + (size_t)e * TDIM;
            const float* mr = msg + (size_t)e * MDIM;
#pragma unroll
            for (int l = 0; l < 6; l++) {
                int f = gf[l];
                float ea = (f < TDIM) ? tr[f] : mr[f - TDIM];
                gacc[l] += (gh1[l] ? w1 : w0) * ea;
            }
        }
        __syncthreads();
    }

    float4* op = (float4*)(out + (size_t)n * DCH + tid * 4);
    float4 o = *op;
    o.x += acc0; o.y += acc1; o.z += acc2; o.w += acc3;
    *op = o;
#pragma unroll
    for (int l = 0; l < 6; l++)
        g_G[(size_t)n * (HEADS * FDIM) + tid * 6 + l] = gacc[l];
}

// ---------------- launch ----------------
extern "C" void kernel_launch(void* const* d_in, const int* in_sizes, int n_in,
                              void* d_out, int out_size)
{
    const float* x     = (const float*)d_in[0];
    // d_in[1] = last_update (unused by reference)
    const int*   ei    = (const int*)d_in[2];
    const float* tfeat = (const float*)d_in[3];
    const float* msg   = (const float*)d_in[4];
    const float* Wq    = (const float*)d_in[5];
    const float* bq    = (const float*)d_in[6];
    const float* Wk    = (const float*)d_in[7];
    const float* bk    = (const float*)d_in[8];
    const float* Wv    = (const float*)d_in[9];
    const float* bv    = (const float*)d_in[10];
    const float* We    = (const float*)d_in[11];
    const float* Ws    = (const float*)d_in[12];
    const float* bs    = (const float*)d_in[13];
    float* out = (float*)d_out;

    float *qp, *kp, *vp, *pp, *wtp, *gp;
    cudaGetSymbolAddress((void**)&qp,  g_q);
    cudaGetSymbolAddress((void**)&kp,  g_k);
    cudaGetSymbolAddress((void**)&vp,  g_v);
    cudaGetSymbolAddress((void**)&pp,  g_p);
    cudaGetSymbolAddress((void**)&wtp, g_WeT);
    cudaGetSymbolAddress((void**)&gp,  g_G);

    // CSR build
    zero_deg_kernel<<<(N_NODES + 255) / 256, 256>>>();
    count_deg_kernel<<<(E_EDGES + 255) / 256, 256>>>(ei);
    scan_kernel<<<1, 1024>>>();
    scatter_perm_kernel<<<(E_EDGES + 255) / 256, 256>>>(ei);

    transpose_we_kernel<<<(HEADS * C_HEAD * FDIM + 255) / 256, 256>>>(We);

    // node projections (q,k,v) + skip directly into out
    dim3 gn(DCH / 64, (N_NODES + 63) / 64);
    gemm64<<<gn, 256>>>(x, DCH, Wq, DCH, qp,  DCH, bq, N_NODES, DCH, DCH, 0);
    gemm64<<<gn, 256>>>(x, DCH, Wk, DCH, kp,  DCH, bk, N_NODES, DCH, DCH, 0);
    gemm64<<<gn, 256>>>(x, DCH, Wv, DCH, vp,  DCH, bv, N_NODES, DCH, DCH, 0);
    gemm64<<<gn, 256>>>(x, DCH, Ws, DCH, out, DCH, bs, N_NODES, DCH, DCH, 0);

    // p = Q_h @ WeT_h   ([N,256] x [256,384] per head)
    dim3 gpd(FDIM / 64, (N_NODES + 63) / 64);
    for (int h = 0; h < HEADS; h++) {
        gemm64<<<gpd, 256>>>(qp + h * C_HEAD, DCH,
                             wtp + (size_t)h * C_HEAD * FDIM, FDIM,
                             pp + h * FDIM, HEADS * FDIM,
                             nullptr, N_NODES, FDIM, C_HEAD, 0);
    }

    // per-edge logits
    edge_alpha_kernel<<<(E_EDGES + 7) / 8, 256>>>(ei, tfeat, msg);

    // per-node softmax + v-aggregation + G accumulation
    aggregate_kernel<<<N_NODES, 128>>>(ei, tfeat, msg, out);

    // out += G_h @ We_h   ([N,384] x [384,256] per head, accumulate)
    dim3 gf(C_HEAD / 64, (N_NODES + 63) / 64);
    for (int h = 0; h < HEADS; h++) {
        gemm64<<<gf, 256>>>(gp + h * FDIM, HEADS * FDIM,
                            We + h * C_HEAD, DCH,
                            out + h * C_HEAD, DCH,
                            nullptr, N_NODES, C_HEAD, FDIM, 1);
    }
}

// round 2
// speedup vs baseline: 1.0019x; 1.0019x over previous
#include <cuda_runtime.h>
#include <math.h>

#define N_NODES 10000
#define E_EDGES 160000
#define DCH 512
#define C_HEAD 256
#define HEADS 2
#define TDIM 128
#define MDIM 256
#define FDIM 384   // TDIM + MDIM

// ---------------- scratch (device globals: no cudaMalloc allowed) ----------------
__device__ float g_q[N_NODES * DCH];
__device__ float g_k[N_NODES * DCH];
__device__ float g_v[N_NODES * DCH];
__device__ float g_p[N_NODES * HEADS * FDIM];      // p[n][h][f] = sum_c q[n,h,c]*We[f,h*C+c]
__device__ float g_WeT[HEADS * C_HEAD * FDIM];     // WeT[h][c][f] = We[f][h*C+c]
__device__ float g_alpha[E_EDGES * HEADS];
__device__ float g_G[N_NODES * HEADS * FDIM];      // G[n][h][f] = sum_{e->n} alpha*ea[f]
__device__ int   g_deg[N_NODES];
__device__ int   g_cur[N_NODES];
__device__ int   g_off[N_NODES + 1];
__device__ int   g_perm[E_EDGES];

// ---------------- fp32 GEMM, 128x128 tile, BK=16, packed f32x2 FMAs --------------
// C[M,N] = A[M,K](lda) * B[K,N](ldb) (+bias)(+=acc).  Requires N%128==0, K%16==0.
// 256 threads, 8x8 microtile split as two 8x4 column groups (cols tx*4 and 64+tx*4).
__global__ void __launch_bounds__(256) gemm128(
    const float* __restrict__ A, int lda,
    const float* __restrict__ B, int ldb,
    float* __restrict__ C, int ldc,
    const float* __restrict__ bias,
    int M, int K, int acc)
{
    __shared__ __align__(16) float As[2][16][136];   // padded row
    __shared__ __align__(16) float Bs[2][16][128];

    const int tid = threadIdx.x;
    const int bm = blockIdx.y * 128, bn = blockIdx.x * 128;
    const int tx = tid & 15, ty = tid >> 4;

    // global A load mapping: 2 rows x float4 per thread
    const int aRow = tid >> 2;          // 0..63
    const int aCol = (tid & 3) * 4;     // 0,4,8,12
    // global B load mapping: 2 float4 per thread
    const int bRow = tid >> 4;          // 0..15
    const int bCol = (tid & 15) * 4;    // 0..60

    const bool aOk0 = (bm + aRow) < M;
    const bool aOk1 = (bm + aRow + 64) < M;
    const float* Ap0 = A + (size_t)(bm + aRow) * lda + aCol;
    const float* Ap1 = A + (size_t)(bm + aRow + 64) * lda + aCol;
    const float* Bp0 = B + (size_t)bRow * ldb + bn + bCol;
    const float* Bp1 = Bp0 + 64;

    const int nkt = K >> 4;

    float4 a0r, a1r, b0r, b1r;
    a0r = aOk0 ? *(const float4*)Ap0 : make_float4(0.f, 0.f, 0.f, 0.f);
    a1r = aOk1 ? *(const float4*)Ap1 : make_float4(0.f, 0.f, 0.f, 0.f);
    b0r = *(const float4*)Bp0;
    b1r = *(const float4*)Bp1;

    As[0][aCol + 0][aRow] = a0r.x;
    As[0][aCol + 1][aRow] = a0r.y;
    As[0][aCol + 2][aRow] = a0r.z;
    As[0][aCol + 3][aRow] = a0r.w;
    As[0][aCol + 0][aRow + 64] = a1r.x;
    As[0][aCol + 1][aRow + 64] = a1r.y;
    As[0][aCol + 2][aRow + 64] = a1r.z;
    As[0][aCol + 3][aRow + 64] = a1r.w;
    *(float4*)&Bs[0][bRow][bCol]      = b0r;
    *(float4*)&Bs[0][bRow][bCol + 64] = b1r;
    __syncthreads();

    // 8 rows x 8 cols accumulators as packed f32x2 (4 pairs per row)
    unsigned long long acc2[8][4];
#pragma unroll
    for (int i = 0; i < 8; i++)
#pragma unroll
        for (int j = 0; j < 4; j++) acc2[i][j] = 0ull;

    for (int kt = 0; kt < nkt; kt++) {
        const int s = kt & 1;
        if (kt + 1 < nkt) {
            const int ko = (kt + 1) * 16;
            a0r = aOk0 ? *(const float4*)(Ap0 + ko) : make_float4(0.f, 0.f, 0.f, 0.f);
            a1r = aOk1 ? *(const float4*)(Ap1 + ko) : make_float4(0.f, 0.f, 0.f, 0.f);
            b0r = *(const float4*)(Bp0 + (size_t)ko * ldb);
            b1r = *(const float4*)(Bp1 + (size_t)ko * ldb);
        }
#pragma unroll
        for (int kk = 0; kk < 16; kk++) {
            float4 av0 = *(const float4*)&As[s][kk][ty * 8];
            float4 av1 = *(const float4*)&As[s][kk][ty * 8 + 4];
            ulonglong2 bv0 = *(const ulonglong2*)&Bs[s][kk][tx * 4];        // cols tx*4..+3
            ulonglong2 bv1 = *(const ulonglong2*)&Bs[s][kk][tx * 4 + 64];   // cols 64+tx*4..+3
            unsigned long long bb[4] = {bv0.x, bv0.y, bv1.x, bv1.y};
            float af[8] = {av0.x, av0.y, av0.z, av0.w, av1.x, av1.y, av1.z, av1.w};
#pragma unroll
            for (int i = 0; i < 8; i++) {
                unsigned long long aa;
                asm("mov.b64 %0, {%1, %1};" : "=l"(aa) : "f"(af[i]));
#pragma unroll
                for (int j = 0; j < 4; j++)
                    asm("fma.rn.f32x2 %0, %1, %2, %0;" : "+l"(acc2[i][j]) : "l"(aa), "l"(bb[j]));
            }
        }
        if (kt + 1 < nkt) {
            __syncthreads();
            const int s1 = s ^ 1;
            As[s1][aCol + 0][aRow] = a0r.x;
            As[s1][aCol + 1][aRow] = a0r.y;
            As[s1][aCol + 2][aRow] = a0r.z;
            As[s1][aCol + 3][aRow] = a0r.w;
            As[s1][aCol + 0][aRow + 64] = a1r.x;
            As[s1][aCol + 1][aRow + 64] = a1r.y;
            As[s1][aCol + 2][aRow + 64] = a1r.z;
            As[s1][aCol + 3][aRow + 64] = a1r.w;
            *(float4*)&Bs[s1][bRow][bCol]      = b0r;
            *(float4*)&Bs[s1][bRow][bCol + 64] = b1r;
            __syncthreads();
        }
    }

    // epilogue
    float bias0[4] = {0.f, 0.f, 0.f, 0.f}, bias1[4] = {0.f, 0.f, 0.f, 0.f};
    if (bias) {
        float4 t0 = *(const float4*)&bias[bn + tx * 4];
        float4 t1 = *(const float4*)&bias[bn + 64 + tx * 4];
        bias0[0] = t0.x; bias0[1] = t0.y; bias0[2] = t0.z; bias0[3] = t0.w;
        bias1[0] = t1.x; bias1[1] = t1.y; bias1[2] = t1.z; bias1[3] = t1.w;
    }
#pragma unroll
    for (int i = 0; i < 8; i++) {
        int row = bm + ty * 8 + i;
        if (row >= M) break;
        float o0[4], o1[4];
        asm("mov.b64 {%0, %1}, %2;" : "=f"(o0[0]), "=f"(o0[1]) : "l"(acc2[i][0]));
        asm("mov.b64 {%0, %1}, %2;" : "=f"(o0[2]), "=f"(o0[3]) : "l"(acc2[i][1]));
        asm("mov.b64 {%0, %1}, %2;" : "=f"(o1[0]), "=f"(o1[1]) : "l"(acc2[i][2]));
        asm("mov.b64 {%0, %1}, %2;" : "=f"(o1[2]), "=f"(o1[3]) : "l"(acc2[i][3]));
        float* c0 = C + (size_t)row * ldc + bn + tx * 4;
        float* c1 = c0 + 64;
        float4 w0, w1;
        if (acc) {
            float4 r0 = *(const float4*)c0;
            float4 r1 = *(const float4*)c1;
            w0 = make_float4(r0.x + o0[0], r0.y + o0[1], r0.z + o0[2], r0.w + o0[3]);
            w1 = make_float4(r1.x + o1[0], r1.y + o1[1], r1.z + o1[2], r1.w + o1[3]);
        } else {
            w0 = make_float4(o0[0] + bias0[0], o0[1] + bias0[1], o0[2] + bias0[2], o0[3] + bias0[3]);
            w1 = make_float4(o1[0] + bias1[0], o1[1] + bias1[1], o1[2] + bias1[2], o1[3] + bias1[3]);
        }
        *(float4*)c0 = w0;
        *(float4*)c1 = w1;
    }
}

// ---------------- CSR build ----------------
__global__ void zero_deg_kernel() {
    int i = blockIdx.x * 256 + threadIdx.x;
    if (i < N_NODES) g_deg[i] = 0;
}

__global__ void count_deg_kernel(const int* __restrict__ ei) {
    int i = blockIdx.x * 256 + threadIdx.x;
    if (i < E_EDGES) atomicAdd(&g_deg[ei[E_EDGES + i]], 1);
}

__global__ void __launch_bounds__(1024) scan_kernel() {
    __shared__ int part[1024];
    int tid = threadIdx.x;
    int base = tid * 10;
    int local[10];
    int s = 0;
#pragma unroll
    for (int j = 0; j < 10; j++) {
        int idx = base + j;
        int d = (idx < N_NODES) ? g_deg[idx] : 0;
        local[j] = d;
        s += d;
    }
    part[tid] = s;
    __syncthreads();
    for (int off = 1; off < 1024; off <<= 1) {
        int v = part[tid];
        int add = (tid >= off) ? part[tid - off] : 0;
        __syncthreads();
        part[tid] = v + add;
        __syncthreads();
    }
    int run = (tid > 0) ? part[tid - 1] : 0;
#pragma unroll
    for (int j = 0; j < 10; j++) {
        int idx = base + j;
        if (idx < N_NODES) {
            g_off[idx] = run;
            run += local[j];
            g_cur[idx] = 0;
        }
    }
    if (tid == 1023) g_off[N_NODES] = part[1023];
}

__global__ void scatter_perm_kernel(const int* __restrict__ ei) {
    int i = blockIdx.x * 256 + threadIdx.x;
    if (i < E_EDGES) {
        int d = ei[E_EDGES + i];
        int p = g_off[d] + atomicAdd(&g_cur[d], 1);
        g_perm[p] = i;
    }
}

// ---------------- We transpose (per head): WeT[h][c][f] = We[f][h*C+c] ----------------
__global__ void transpose_we_kernel(const float* __restrict__ We) {
    int i = blockIdx.x * 256 + threadIdx.x;
    if (i < HEADS * C_HEAD * FDIM) {
        int h = i / (C_HEAD * FDIM);
        int r = i % (C_HEAD * FDIM);
        int c = r / FDIM;
        int f = r % FDIM;
        g_WeT[i] = We[(size_t)f * DCH + h * C_HEAD + c];
    }
}

// ---------------- per-edge attention logits (warp per edge) ----------------
// alpha[e,h] = ( q[dst]_h . k[src]_h  +  ea[e] . p[dst]_h ) / 16
__global__ void __launch_bounds__(256) edge_alpha_kernel(
    const int* __restrict__ ei, const float* __restrict__ tfeat,
    const float* __restrict__ msg)
{
    int w = (blockIdx.x * 256 + threadIdx.x) >> 5;
    int lane = threadIdx.x & 31;
    if (w >= E_EDGES) return;
    int src = ei[w];
    int dst = ei[E_EDGES + w];
    const float* qr = g_q + (size_t)dst * DCH;
    const float* kr = g_k + (size_t)src * DCH;
    const float* pr = g_p + (size_t)dst * (HEADS * FDIM);
    float a0 = 0.f, a1 = 0.f;
    for (int c = lane; c < C_HEAD; c += 32) {
        a0 += qr[c] * kr[c];
        a1 += qr[c + C_HEAD] * kr[c + C_HEAD];
    }
    const float* tr = tfeat + (size_t)w * TDIM;
    for (int f = lane; f < TDIM; f += 32) {
        float e = tr[f];
        a0 += e * pr[f];
        a1 += e * pr[FDIM + f];
    }
    const float* mr = msg + (size_t)w * MDIM;
    for (int f = lane; f < MDIM; f += 32) {
        float e = mr[f];
        a0 += e * pr[TDIM + f];
        a1 += e * pr[FDIM + TDIM + f];
    }
#pragma unroll
    for (int o = 16; o; o >>= 1) {
        a0 += __shfl_xor_sync(0xffffffffu, a0, o);
        a1 += __shfl_xor_sync(0xffffffffu, a1, o);
    }
    if (lane == 0) {
        g_alpha[2 * w + 0] = a0 * 0.0625f;   // / sqrt(256)
        g_alpha[2 * w + 1] = a1 * 0.0625f;
    }
}

// ---------------- per-node softmax + aggregation (block of 128 per node) ----------------
__global__ void __launch_bounds__(128) aggregate_kernel(
    const int* __restrict__ ei, const float* __restrict__ tfeat,
    const float* __restrict__ msg, float* __restrict__ out)
{
    int n = blockIdx.x;
    int tid = threadIdx.x;
    int beg = g_off[n], end = g_off[n + 1];
    int deg = end - beg;

    if (deg == 0) {
#pragma unroll
        for (int l = 0; l < 6; l++)
            g_G[(size_t)n * (HEADS * FDIM) + tid * 6 + l] = 0.f;
        return;
    }

    __shared__ float red0[128], red1[128];

    float m0 = -1e30f, m1 = -1e30f;
    for (int i = tid; i < deg; i += 128) {
        int e = g_perm[beg + i];
        m0 = fmaxf(m0, g_alpha[2 * e + 0]);
        m1 = fmaxf(m1, g_alpha[2 * e + 1]);
    }
    red0[tid] = m0; red1[tid] = m1;
    __syncthreads();
    for (int s = 64; s; s >>= 1) {
        if (tid < s) {
            red0[tid] = fmaxf(red0[tid], red0[tid + s]);
            red1[tid] = fmaxf(red1[tid], red1[tid + s]);
        }
        __syncthreads();
    }
    float amax0 = red0[0], amax1 = red1[0];
    __syncthreads();

    float d0 = 0.f, d1 = 0.f;
    for (int i = tid; i < deg; i += 128) {
        int e = g_perm[beg + i];
        d0 += expf(g_alpha[2 * e + 0] - amax0);
        d1 += expf(g_alpha[2 * e + 1] - amax1);
    }
    red0[tid] = d0; red1[tid] = d1;
    __syncthreads();
    for (int s = 64; s; s >>= 1) {
        if (tid < s) {
            red0[tid] += red0[tid + s];
            red1[tid] += red1[tid + s];
        }
        __syncthreads();
    }
    float inv0 = 1.f / (red0[0] + 1e-16f);
    float inv1 = 1.f / (red1[0] + 1e-16f);
    __syncthreads();

    __shared__ int s_eid[128];
    __shared__ int s_src[128];
    __shared__ float s_w0[128], s_w1[128];

    float acc0 = 0.f, acc1 = 0.f, acc2 = 0.f, acc3 = 0.f;
    float gacc[6] = {0.f, 0.f, 0.f, 0.f, 0.f, 0.f};

    int gf[6]; bool gh1[6];
#pragma unroll
    for (int l = 0; l < 6; l++) {
        int idx = tid * 6 + l;
        gh1[l] = (idx >= FDIM);
        gf[l] = gh1[l] ? idx - FDIM : idx;
    }

    for (int base = 0; base < deg; base += 128) {
        int cnt = min(128, deg - base);
        if (tid < cnt) {
            int e = g_perm[beg + base + tid];
            s_eid[tid] = e;
            s_src[tid] = ei[e];
            s_w0[tid] = expf(g_alpha[2 * e + 0] - amax0) * inv0;
            s_w1[tid] = expf(g_alpha[2 * e + 1] - amax1) * inv1;
        }
        __syncthreads();
        for (int j = 0; j < cnt; j++) {
            int e = s_eid[j];
            int src = s_src[j];
            float w0 = s_w0[j], w1 = s_w1[j];
            float wv = (tid < 64) ? w0 : w1;
            float4 vv = *(const float4*)(g_v + (size_t)src * DCH + tid * 4);
            acc0 += wv * vv.x; acc1 += wv * vv.y; acc2 += wv * vv.z; acc3 += wv * vv.w;
            const float* tr = tfeat + (size_t)e * TDIM;
            const float* mr = msg + (size_t)e * MDIM;
#pragma unroll
            for (int l = 0; l < 6; l++) {
                int f = gf[l];
                float ea = (f < TDIM) ? tr[f] : mr[f - TDIM];
                gacc[l] += (gh1[l] ? w1 : w0) * ea;
            }
        }
        __syncthreads();
    }

    float4* op = (float4*)(out + (size_t)n * DCH + tid * 4);
    float4 o = *op;
    o.x += acc0; o.y += acc1; o.z += acc2; o.w += acc3;
    *op = o;
#pragma unroll
    for (int l = 0; l < 6; l++)
        g_G[(size_t)n * (HEADS * FDIM) + tid * 6 + l] = gacc[l];
}

// ---------------- launch ----------------
extern "C" void kernel_launch(void* const* d_in, const int* in_sizes, int n_in,
                              void* d_out, int out_size)
{
    const float* x     = (const float*)d_in[0];
    const int*   ei    = (const int*)d_in[2];
    const float* tfeat = (const float*)d_in[3];
    const float* msg   = (const float*)d_in[4];
    const float* Wq    = (const float*)d_in[5];
    const float* bq    = (const float*)d_in[6];
    const float* Wk    = (const float*)d_in[7];
    const float* bk    = (const float*)d_in[8];
    const float* Wv    = (const float*)d_in[9];
    const float* bv    = (const float*)d_in[10];
    const float* We    = (const float*)d_in[11];
    const float* Ws    = (const float*)d_in[12];
    const float* bs    = (const float*)d_in[13];
    float* out = (float*)d_out;

    float *qp, *kp, *vp, *pp, *wtp, *gp;
    cudaGetSymbolAddress((void**)&qp,  g_q);
    cudaGetSymbolAddress((void**)&kp,  g_k);
    cudaGetSymbolAddress((void**)&vp,  g_v);
    cudaGetSymbolAddress((void**)&pp,  g_p);
    cudaGetSymbolAddress((void**)&wtp, g_WeT);
    cudaGetSymbolAddress((void**)&gp,  g_G);

    // CSR build
    zero_deg_kernel<<<(N_NODES + 255) / 256, 256>>>();
    count_deg_kernel<<<(E_EDGES + 255) / 256, 256>>>(ei);
    scan_kernel<<<1, 1024>>>();
    scatter_perm_kernel<<<(E_EDGES + 255) / 256, 256>>>(ei);

    transpose_we_kernel<<<(HEADS * C_HEAD * FDIM + 255) / 256, 256>>>(We);

    // node projections (q,k,v) + skip directly into out
    dim3 gn(DCH / 128, (N_NODES + 127) / 128);
    gemm128<<<gn, 256>>>(x, DCH, Wq, DCH, qp,  DCH, bq, N_NODES, DCH, 0);
    gemm128<<<gn, 256>>>(x, DCH, Wk, DCH, kp,  DCH, bk, N_NODES, DCH, 0);
    gemm128<<<gn, 256>>>(x, DCH, Wv, DCH, vp,  DCH, bv, N_NODES, DCH, 0);
    gemm128<<<gn, 256>>>(x, DCH, Ws, DCH, out, DCH, bs, N_NODES, DCH, 0);

    // p = Q_h @ WeT_h   ([N,256] x [256,384] per head)
    dim3 gpd(FDIM / 128, (N_NODES + 127) / 128);
    for (int h = 0; h < HEADS; h++) {
        gemm128<<<gpd, 256>>>(qp + h * C_HEAD, DCH,
                              wtp + (size_t)h * C_HEAD * FDIM, FDIM,
                              pp + h * FDIM, HEADS * FDIM,
                              nullptr, N_NODES, C_HEAD, 0);
    }

    // per-edge logits
    edge_alpha_kernel<<<(E_EDGES + 7) / 8, 256>>>(ei, tfeat, msg);

    // per-node softmax + v-aggregation + G accumulation
    aggregate_kernel<<<N_NODES, 128>>>(ei, tfeat, msg, out);

    // out += G_h @ We_h   ([N,384] x [384,256] per head, accumulate)
    dim3 gf(C_HEAD / 128, (N_NODES + 127) / 128);
    for (int h = 0; h < HEADS; h++) {
        gemm128<<<gf, 256>>>(gp + h * FDIM, HEADS * FDIM,
                             We + h * C_HEAD, DCH,
                             out + h * C_HEAD, DCH,
                             nullptr, N_NODES, FDIM, 1);
    }
}

// round 3
// speedup vs baseline: 1.4021x; 1.3994x over previous
#include <cuda_runtime.h>
#include <math.h>

#define N_NODES 10000
#define E_EDGES 160000
#define DCH 512
#define C_HEAD 256
#define HEADS 2
#define TDIM 128
#define MDIM 256
#define FDIM 384   // TDIM + MDIM

// ---------------- scratch (device globals: no cudaMalloc allowed) ----------------
__device__ float  g_q[N_NODES * DCH];
__device__ float  g_k[N_NODES * DCH];
__device__ float  g_v[N_NODES * DCH];
__device__ float  g_p[N_NODES * HEADS * FDIM];     // p[n][h][f] = sum_c q[n,h,c]*We[f,h*C+c]
__device__ float  g_WeT[HEADS * C_HEAD * FDIM];    // WeT[h][c][f] = We[f][h*C+c]
__device__ float2 g_alpha2[E_EDGES];               // logits in CSR slot order
__device__ float  g_G[N_NODES * HEADS * FDIM];
__device__ int    g_deg[N_NODES];
__device__ int    g_cur[N_NODES];
__device__ int    g_off[N_NODES + 1];
__device__ int    g_perm[E_EDGES];

// ---------------- fp32 GEMM tile body: 128x128, BK=16, packed f32x2 FMAs ----------
__device__ __forceinline__ void gemm_tile(
    const float* __restrict__ A, int lda,
    const float* __restrict__ B, int ldb,
    float* __restrict__ C, int ldc,
    const float* __restrict__ bias,
    int M, int K, int acc, int bm, int bn,
    float As[2][16][136], float Bs[2][16][128])
{
    const int tid = threadIdx.x;
    const int tx = tid & 15, ty = tid >> 4;

    const int aRow = tid >> 2;
    const int aCol = (tid & 3) * 4;
    const int bRow = tid >> 4;
    const int bCol = (tid & 15) * 4;

    const bool aOk0 = (bm + aRow) < M;
    const bool aOk1 = (bm + aRow + 64) < M;
    const float* Ap0 = A + (size_t)(bm + aRow) * lda + aCol;
    const float* Ap1 = A + (size_t)(bm + aRow + 64) * lda + aCol;
    const float* Bp0 = B + (size_t)bRow * ldb + bn + bCol;
    const float* Bp1 = Bp0 + 64;

    const int nkt = K >> 4;

    float4 a0r, a1r, b0r, b1r;
    a0r = aOk0 ? *(const float4*)Ap0 : make_float4(0.f, 0.f, 0.f, 0.f);
    a1r = aOk1 ? *(const float4*)Ap1 : make_float4(0.f, 0.f, 0.f, 0.f);
    b0r = *(const float4*)Bp0;
    b1r = *(const float4*)Bp1;

    As[0][aCol + 0][aRow] = a0r.x;
    As[0][aCol + 1][aRow] = a0r.y;
    As[0][aCol + 2][aRow] = a0r.z;
    As[0][aCol + 3][aRow] = a0r.w;
    As[0][aCol + 0][aRow + 64] = a1r.x;
    As[0][aCol + 1][aRow + 64] = a1r.y;
    As[0][aCol + 2][aRow + 64] = a1r.z;
    As[0][aCol + 3][aRow + 64] = a1r.w;
    *(float4*)&Bs[0][bRow][bCol]      = b0r;
    *(float4*)&Bs[0][bRow][bCol + 64] = b1r;
    __syncthreads();

    unsigned long long acc2[8][4];
#pragma unroll
    for (int i = 0; i < 8; i++)
#pragma unroll
        for (int j = 0; j < 4; j++) acc2[i][j] = 0ull;

    for (int kt = 0; kt < nkt; kt++) {
        const int s = kt & 1;
        if (kt + 1 < nkt) {
            const int ko = (kt + 1) * 16;
            a0r = aOk0 ? *(const float4*)(Ap0 + ko) : make_float4(0.f, 0.f, 0.f, 0.f);
            a1r = aOk1 ? *(const float4*)(Ap1 + ko) : make_float4(0.f, 0.f, 0.f, 0.f);
            b0r = *(const float4*)(Bp0 + (size_t)ko * ldb);
            b1r = *(const float4*)(Bp1 + (size_t)ko * ldb);
        }
#pragma unroll
        for (int kk = 0; kk < 16; kk++) {
            float4 av0 = *(const float4*)&As[s][kk][ty * 8];
            float4 av1 = *(const float4*)&As[s][kk][ty * 8 + 4];
            ulonglong2 bv0 = *(const ulonglong2*)&Bs[s][kk][tx * 4];
            ulonglong2 bv1 = *(const ulonglong2*)&Bs[s][kk][tx * 4 + 64];
            unsigned long long bb[4] = {bv0.x, bv0.y, bv1.x, bv1.y};
            float af[8] = {av0.x, av0.y, av0.z, av0.w, av1.x, av1.y, av1.z, av1.w};
#pragma unroll
            for (int i = 0; i < 8; i++) {
                unsigned long long aa;
                asm("mov.b64 %0, {%1, %1};" : "=l"(aa) : "f"(af[i]));
#pragma unroll
                for (int j = 0; j < 4; j++)
                    asm("fma.rn.f32x2 %0, %1, %2, %0;" : "+l"(acc2[i][j]) : "l"(aa), "l"(bb[j]));
            }
        }
        if (kt + 1 < nkt) {
            __syncthreads();
            const int s1 = s ^ 1;
            As[s1][aCol + 0][aRow] = a0r.x;
            As[s1][aCol + 1][aRow] = a0r.y;
            As[s1][aCol + 2][aRow] = a0r.z;
            As[s1][aCol + 3][aRow] = a0r.w;
            As[s1][aCol + 0][aRow + 64] = a1r.x;
            As[s1][aCol + 1][aRow + 64] = a1r.y;
            As[s1][aCol + 2][aRow + 64] = a1r.z;
            As[s1][aCol + 3][aRow + 64] = a1r.w;
            *(float4*)&Bs[s1][bRow][bCol]      = b0r;
            *(float4*)&Bs[s1][bRow][bCol + 64] = b1r;
            __syncthreads();
        }
    }

    float bias0[4] = {0.f, 0.f, 0.f, 0.f}, bias1[4] = {0.f, 0.f, 0.f, 0.f};
    if (bias) {
        float4 t0 = *(const float4*)&bias[bn + tx * 4];
        float4 t1 = *(const float4*)&bias[bn + 64 + tx * 4];
        bias0[0] = t0.x; bias0[1] = t0.y; bias0[2] = t0.z; bias0[3] = t0.w;
        bias1[0] = t1.x; bias1[1] = t1.y; bias1[2] = t1.z; bias1[3] = t1.w;
    }
#pragma unroll
    for (int i = 0; i < 8; i++) {
        int row = bm + ty * 8 + i;
        if (row >= M) break;
        float o0[4], o1[4];
        asm("mov.b64 {%0, %1}, %2;" : "=f"(o0[0]), "=f"(o0[1]) : "l"(acc2[i][0]));
        asm("mov.b64 {%0, %1}, %2;" : "=f"(o0[2]), "=f"(o0[3]) : "l"(acc2[i][1]));
        asm("mov.b64 {%0, %1}, %2;" : "=f"(o1[0]), "=f"(o1[1]) : "l"(acc2[i][2]));
        asm("mov.b64 {%0, %1}, %2;" : "=f"(o1[2]), "=f"(o1[3]) : "l"(acc2[i][3]));
        float* c0 = C + (size_t)row * ldc + bn + tx * 4;
        float* c1 = c0 + 64;
        float4 w0, w1;
        if (acc) {
            float4 r0 = *(const float4*)c0;
            float4 r1 = *(const float4*)c1;
            w0 = make_float4(r0.x + o0[0], r0.y + o0[1], r0.z + o0[2], r0.w + o0[3]);
            w1 = make_float4(r1.x + o1[0], r1.y + o1[1], r1.z + o1[2], r1.w + o1[3]);
        } else {
            w0 = make_float4(o0[0] + bias0[0], o0[1] + bias0[1], o0[2] + bias0[2], o0[3] + bias0[3]);
            w1 = make_float4(o1[0] + bias1[0], o1[1] + bias1[1], o1[2] + bias1[2], o1[3] + bias1[3]);
        }
        *(float4*)c0 = w0;
        *(float4*)c1 = w1;
    }
}

// generic GEMM kernel
__global__ void __launch_bounds__(256) gemm128(
    const float* __restrict__ A, int lda,
    const float* __restrict__ B, int ldb,
    float* __restrict__ C, int ldc,
    const float* __restrict__ bias,
    int M, int K, int acc)
{
    __shared__ __align__(16) float As[2][16][136];
    __shared__ __align__(16) float Bs[2][16][128];
    gemm_tile(A, lda, B, ldb, C, ldc, bias, M, K, acc,
              blockIdx.y * 128, blockIdx.x * 128, As, Bs);
}

// fused q/k/v/skip projection: grid.x = 16 (4 matrices x 4 col tiles)
__global__ void __launch_bounds__(256) gemm_qkvs(
    const float* __restrict__ x,
    const float* __restrict__ Wq, const float* __restrict__ bq,
    const float* __restrict__ Wk, const float* __restrict__ bk,
    const float* __restrict__ Wv, const float* __restrict__ bv,
    const float* __restrict__ Ws, const float* __restrict__ bs,
    float* __restrict__ out)
{
    __shared__ __align__(16) float As[2][16][136];
    __shared__ __align__(16) float Bs[2][16][128];
    int w = blockIdx.x >> 2;
    int bn = (blockIdx.x & 3) * 128;
    const float* B; const float* bias; float* C;
    if (w == 0)      { B = Wq; bias = bq; C = g_q; }
    else if (w == 1) { B = Wk; bias = bk; C = g_k; }
    else if (w == 2) { B = Wv; bias = bv; C = g_v; }
    else             { B = Ws; bias = bs; C = out; }
    gemm_tile(x, DCH, B, DCH, C, DCH, bias, N_NODES, DCH, 0,
              blockIdx.y * 128, bn, As, Bs);
}

// ---------------- CSR build ----------------
__global__ void zero_deg_kernel() {
    int i = blockIdx.x * 256 + threadIdx.x;
    if (i < N_NODES) g_deg[i] = 0;
}

__global__ void count_deg_kernel(const int* __restrict__ ei) {
    int i = blockIdx.x * 256 + threadIdx.x;
    if (i < E_EDGES) atomicAdd(&g_deg[ei[E_EDGES + i]], 1);
}

__global__ void __launch_bounds__(1024) scan_kernel() {
    __shared__ int part[1024];
    int tid = threadIdx.x;
    int base = tid * 10;
    int local[10];
    int s = 0;
#pragma unroll
    for (int j = 0; j < 10; j++) {
        int idx = base + j;
        int d = (idx < N_NODES) ? g_deg[idx] : 0;
        local[j] = d;
        s += d;
    }
    part[tid] = s;
    __syncthreads();
    for (int off = 1; off < 1024; off <<= 1) {
        int v = part[tid];
        int add = (tid >= off) ? part[tid - off] : 0;
        __syncthreads();
        part[tid] = v + add;
        __syncthreads();
    }
    int run = (tid > 0) ? part[tid - 1] : 0;
#pragma unroll
    for (int j = 0; j < 10; j++) {
        int idx = base + j;
        if (idx < N_NODES) {
            g_off[idx] = run;
            run += local[j];
            g_cur[idx] = 0;
        }
    }
    if (tid == 1023) g_off[N_NODES] = part[1023];
}

__global__ void scatter_perm_kernel(const int* __restrict__ ei) {
    int i = blockIdx.x * 256 + threadIdx.x;
    if (i < E_EDGES) {
        int d = ei[E_EDGES + i];
        int p = g_off[d] + atomicAdd(&g_cur[d], 1);
        g_perm[p] = i;
    }
}

// ---------------- We transpose ----------------
__global__ void transpose_we_kernel(const float* __restrict__ We) {
    int i = blockIdx.x * 256 + threadIdx.x;
    if (i < HEADS * C_HEAD * FDIM) {
        int h = i / (C_HEAD * FDIM);
        int r = i % (C_HEAD * FDIM);
        int c = r / FDIM;
        int f = r % FDIM;
        g_WeT[i] = We[(size_t)f * DCH + h * C_HEAD + c];
    }
}

// ---------------- CSR-grouped per-edge logits: one block per dst node ----------------
// q[dst] and p[dst] staged in SMEM; per edge gather only k[src] + edge_attr (float4).
__global__ void __launch_bounds__(128) edge_alpha_kernel(
    const int* __restrict__ ei, const float* __restrict__ tfeat,
    const float* __restrict__ msg)
{
    int n = blockIdx.x;
    int beg = g_off[n];
    int deg = g_off[n + 1] - beg;
    if (deg == 0) return;

    __shared__ __align__(16) float sq[DCH];
    __shared__ __align__(16) float sp[HEADS * FDIM];
    int tid = threadIdx.x;
    ((float4*)sq)[tid] = ((const float4*)(g_q + (size_t)n * DCH))[tid];
    const float4* pr4 = (const float4*)(g_p + (size_t)n * (HEADS * FDIM));
#pragma unroll
    for (int i = tid; i < (HEADS * FDIM) / 4; i += 128)
        ((float4*)sp)[i] = pr4[i];
    __syncthreads();

    int wid = tid >> 5, lane = tid & 31;
    for (int i = wid; i < deg; i += 4) {
        int slot = beg + i;
        int e = g_perm[slot];
        int src = ei[e];
        const float4* kr = (const float4*)(g_k + (size_t)src * DCH);
        float a0 = 0.f, a1 = 0.f;
#pragma unroll
        for (int it = 0; it < 2; it++) {
            float4 kv = kr[lane + 32 * it];
            float4 qv = *(const float4*)&sq[(lane + 32 * it) * 4];
            a0 += kv.x * qv.x + kv.y * qv.y + kv.z * qv.z + kv.w * qv.w;
        }
#pragma unroll
        for (int it = 2; it < 4; it++) {
            float4 kv = kr[lane + 32 * it];
            float4 qv = *(const float4*)&sq[(lane + 32 * it) * 4];
            a1 += kv.x * qv.x + kv.y * qv.y + kv.z * qv.z + kv.w * qv.w;
        }
        // time features -> p[0..127]
        {
            float4 tv = ((const float4*)(tfeat + (size_t)e * TDIM))[lane];
            float4 p0 = *(const float4*)&sp[lane * 4];
            float4 p1 = *(const float4*)&sp[FDIM + lane * 4];
            a0 += tv.x * p0.x + tv.y * p0.y + tv.z * p0.z + tv.w * p0.w;
            a1 += tv.x * p1.x + tv.y * p1.y + tv.z * p1.z + tv.w * p1.w;
        }
        // msg features -> p[128..383]
        const float4* mr4 = (const float4*)(msg + (size_t)e * MDIM);
#pragma unroll
        for (int it = 0; it < 2; it++) {
            float4 mv = mr4[lane + 32 * it];
            int f = TDIM + (lane + 32 * it) * 4;
            float4 p0 = *(const float4*)&sp[f];
            float4 p1 = *(const float4*)&sp[FDIM + f];
            a0 += mv.x * p0.x + mv.y * p0.y + mv.z * p0.z + mv.w * p0.w;
            a1 += mv.x * p1.x + mv.y * p1.y + mv.z * p1.z + mv.w * p1.w;
        }
#pragma unroll
        for (int o = 16; o; o >>= 1) {
            a0 += __shfl_xor_sync(0xffffffffu, a0, o);
            a1 += __shfl_xor_sync(0xffffffffu, a1, o);
        }
        if (lane == 0)
            g_alpha2[slot] = make_float2(a0 * 0.0625f, a1 * 0.0625f);
    }
}

// ---------------- per-node softmax + aggregation ----------------
__global__ void __launch_bounds__(128) aggregate_kernel(
    const int* __restrict__ ei, const float* __restrict__ tfeat,
    const float* __restrict__ msg, float* __restrict__ out)
{
    int n = blockIdx.x;
    int tid = threadIdx.x;
    int beg = g_off[n], end = g_off[n + 1];
    int deg = end - beg;

    if (deg == 0) {
#pragma unroll
        for (int l = 0; l < 6; l++)
            g_G[(size_t)n * (HEADS * FDIM) + tid * 6 + l] = 0.f;
        return;
    }

    __shared__ float red0[128], red1[128];

    float m0 = -1e30f, m1 = -1e30f;
    for (int i = tid; i < deg; i += 128) {
        float2 a = g_alpha2[beg + i];
        m0 = fmaxf(m0, a.x);
        m1 = fmaxf(m1, a.y);
    }
    red0[tid] = m0; red1[tid] = m1;
    __syncthreads();
    for (int s = 64; s; s >>= 1) {
        if (tid < s) {
            red0[tid] = fmaxf(red0[tid], red0[tid + s]);
            red1[tid] = fmaxf(red1[tid], red1[tid + s]);
        }
        __syncthreads();
    }
    float amax0 = red0[0], amax1 = red1[0];
    __syncthreads();

    float d0 = 0.f, d1 = 0.f;
    for (int i = tid; i < deg; i += 128) {
        float2 a = g_alpha2[beg + i];
        d0 += expf(a.x - amax0);
        d1 += expf(a.y - amax1);
    }
    red0[tid] = d0; red1[tid] = d1;
    __syncthreads();
    for (int s = 64; s; s >>= 1) {
        if (tid < s) {
            red0[tid] += red0[tid + s];
            red1[tid] += red1[tid + s];
        }
        __syncthreads();
    }
    float inv0 = 1.f / (red0[0] + 1e-16f);
    float inv1 = 1.f / (red1[0] + 1e-16f);
    __syncthreads();

    __shared__ int s_eid[128];
    __shared__ int s_src[128];
    __shared__ float s_w0[128], s_w1[128];

    float acc0 = 0.f, acc1 = 0.f, acc2 = 0.f, acc3 = 0.f;
    float gacc[6] = {0.f, 0.f, 0.f, 0.f, 0.f, 0.f};

    int gf[6]; bool gh1[6];
#pragma unroll
    for (int l = 0; l < 6; l++) {
        int idx = tid * 6 + l;
        gh1[l] = (idx >= FDIM);
        gf[l] = gh1[l] ? idx - FDIM : idx;
    }

    for (int base = 0; base < deg; base += 128) {
        int cnt = min(128, deg - base);
        if (tid < cnt) {
            int slot = beg + base + tid;
            int e = g_perm[slot];
            float2 a = g_alpha2[slot];
            s_eid[tid] = e;
            s_src[tid] = ei[e];
            s_w0[tid] = expf(a.x - amax0) * inv0;
            s_w1[tid] = expf(a.y - amax1) * inv1;
        }
        __syncthreads();
        for (int j = 0; j < cnt; j++) {
            int e = s_eid[j];
            int src = s_src[j];
            float w0 = s_w0[j], w1 = s_w1[j];
            float wv = (tid < 64) ? w0 : w1;
            float4 vv = *(const float4*)(g_v + (size_t)src * DCH + tid * 4);
            acc0 += wv * vv.x; acc1 += wv * vv.y; acc2 += wv * vv.z; acc3 += wv * vv.w;
            const float* tr = tfeat + (size_t)e * TDIM;
            const float* mr = msg + (size_t)e * MDIM;
#pragma unroll
            for (int l = 0; l < 6; l++) {
                int f = gf[l];
                float ea = (f < TDIM) ? tr[f] : mr[f - TDIM];
                gacc[l] += (gh1[l] ? w1 : w0) * ea;
            }
        }
        __syncthreads();
    }

    float4* op = (float4*)(out + (size_t)n * DCH + tid * 4);
    float4 o = *op;
    o.x += acc0; o.y += acc1; o.z += acc2; o.w += acc3;
    *op = o;
#pragma unroll
    for (int l = 0; l < 6; l++)
        g_G[(size_t)n * (HEADS * FDIM) + tid * 6 + l] = gacc[l];
}

// ---------------- launch ----------------
extern "C" void kernel_launch(void* const* d_in, const int* in_sizes, int n_in,
                              void* d_out, int out_size)
{
    const float* x     = (const float*)d_in[0];
    const int*   ei    = (const int*)d_in[2];
    const float* tfeat = (const float*)d_in[3];
    const float* msg   = (const float*)d_in[4];
    const float* Wq    = (const float*)d_in[5];
    const float* bq    = (const float*)d_in[6];
    const float* Wk    = (const float*)d_in[7];
    const float* bk    = (const float*)d_in[8];
    const float* Wv    = (const float*)d_in[9];
    const float* bv    = (const float*)d_in[10];
    const float* We    = (const float*)d_in[11];
    const float* Ws    = (const float*)d_in[12];
    const float* bs    = (const float*)d_in[13];
    float* out = (float*)d_out;

    float *qp, *wtp, *pp, *gp;
    cudaGetSymbolAddress((void**)&qp,  g_q);
    cudaGetSymbolAddress((void**)&wtp, g_WeT);
    cudaGetSymbolAddress((void**)&pp,  g_p);
    cudaGetSymbolAddress((void**)&gp,  g_G);

    // 1-3: CSR prefix
    zero_deg_kernel<<<(N_NODES + 255) / 256, 256>>>();
    count_deg_kernel<<<(E_EDGES + 255) / 256, 256>>>(ei);
    scan_kernel<<<1, 1024>>>();

    // 4: fused q/k/v/skip projections  <-- profiled slot
    dim3 gqkvs(16, (N_NODES + 127) / 128);
    gemm_qkvs<<<gqkvs, 256>>>(x, Wq, bq, Wk, bk, Wv, bv, Ws, bs, out);

    // 5-6
    scatter_perm_kernel<<<(E_EDGES + 255) / 256, 256>>>(ei);
    transpose_we_kernel<<<(HEADS * C_HEAD * FDIM + 255) / 256, 256>>>(We);

    // 7-8: p = Q_h @ WeT_h
    dim3 gpd(FDIM / 128, (N_NODES + 127) / 128);
    for (int h = 0; h < HEADS; h++) {
        gemm128<<<gpd, 256>>>(qp + h * C_HEAD, DCH,
                              wtp + (size_t)h * C_HEAD * FDIM, FDIM,
                              pp + h * FDIM, HEADS * FDIM,
                              nullptr, N_NODES, C_HEAD, 0);
    }

    // 9: CSR-grouped edge logits
    edge_alpha_kernel<<<N_NODES, 128>>>(ei, tfeat, msg);

    // 10: per-node softmax + aggregation
    aggregate_kernel<<<N_NODES, 128>>>(ei, tfeat, msg, out);

    // 11-12: out += G_h @ We_h
    dim3 gfd(C_HEAD / 128, (N_NODES + 127) / 128);
    for (int h = 0; h < HEADS; h++) {
        gemm128<<<gfd, 256>>>(gp + h * FDIM, HEADS * FDIM,
                              We + h * C_HEAD, DCH,
                              out + h * C_HEAD, DCH,
                              nullptr, N_NODES, FDIM, 1);
    }
}

// round 5
// speedup vs baseline: 1.6616x; 1.1851x over previous
#include <cuda_runtime.h>
#include <cuda_bf16.h>
#include <math.h>
#include <stdint.h>

#define N_NODES 10000
#define E_EDGES 160000
#define DCH 512
#define C_HEAD 256
#define HEADS 2
#define TDIM 128
#define MDIM 256
#define FDIM 384   // TDIM + MDIM
#define NCAT 2816  // 4*512 (q,k,v,skip) + 2*384 (p heads)

// ---------------- scratch (device globals) ----------------
__device__ float  g_q[N_NODES * DCH];
__device__ float  g_k[N_NODES * DCH];
__device__ float  g_v[N_NODES * DCH];
__device__ float  g_p[N_NODES * HEADS * FDIM];
__device__ float  g_WeT[HEADS * C_HEAD * FDIM];       // WeT[h][c][f] = We[f][h*C+c]
__device__ float  g_pbias[HEADS * FDIM];
__device__ float2 g_alpha2[E_EDGES];
__device__ int    g_deg[N_NODES];
__device__ int    g_cur[N_NODES];
__device__ int    g_off[N_NODES + 1];
__device__ int    g_perm[E_EDGES];
// split-bf16 operands
__device__ __nv_bfloat16 g_xhi[N_NODES * DCH];
__device__ __nv_bfloat16 g_xlo[N_NODES * DCH];
__device__ __nv_bfloat16 g_whi[NCAT * DCH];                // K-major: [n][k]
__device__ __nv_bfloat16 g_wlo[NCAT * DCH];
__device__ __nv_bfloat16 g_wekthi[HEADS * C_HEAD * FDIM];  // [h][n][k] n<256,k<384
__device__ __nv_bfloat16 g_wektlo[HEADS * C_HEAD * FDIM];
__device__ __nv_bfloat16 g_ghi[N_NODES * HEADS * FDIM];    // [n][h*384+f]
__device__ __nv_bfloat16 g_glo[N_NODES * HEADS * FDIM];

// ================= mma.sync bf16 helpers =================
__device__ __forceinline__ void mma_bf16_acc(
    float c[4], uint32_t a0, uint32_t a1, uint32_t a2, uint32_t a3,
    uint32_t b0, uint32_t b1)
{
    asm volatile(
        "mma.sync.aligned.m16n8k16.row.col.f32.bf16.bf16.f32 "
        "{%0,%1,%2,%3}, {%4,%5,%6,%7}, {%8,%9}, {%0,%1,%2,%3};"
        : "+f"(c[0]), "+f"(c[1]), "+f"(c[2]), "+f"(c[3])
        : "r"(a0), "r"(a1), "r"(a2), "r"(a3), "r"(b0), "r"(b1));
}

#define LDK 24   // padded k-stride in bf16 (16 data + 8 pad) -> conflict-free frag LDS

// ---------------- mma mainloop: 128x128 CTA tile, BK=16, split-bf16 3-product ----
// cacc[mt][nt][4] += (Ahi+Alo)[128 rows @ m0][K] * (Bhi+Blo)[128 rows @ n0][K]^T
__device__ __forceinline__ void mma_mainloop(
    const __nv_bfloat16* __restrict__ Ahi, const __nv_bfloat16* __restrict__ Alo,
    int lda, int m0, int Mrows,
    const __nv_bfloat16* __restrict__ Bhi, const __nv_bfloat16* __restrict__ Blo,
    int ldb, int n0, int K,
    float cacc[4][4][4])
{
    __shared__ __align__(16) __nv_bfloat16 sAh[128 * LDK];
    __shared__ __align__(16) __nv_bfloat16 sAl[128 * LDK];
    __shared__ __align__(16) __nv_bfloat16 sBh[128 * LDK];
    __shared__ __align__(16) __nv_bfloat16 sBl[128 * LDK];

    const int tid = threadIdx.x;
    const int row = tid >> 1;              // 0..127
    const int colh = (tid & 1) * 8;        // 0 or 8
    const int lane = tid & 31;
    const int wid = tid >> 5;
    const int wm = (wid & 1) * 64;         // warp m-offset
    const int wn = (wid >> 1) * 32;        // warp n-offset
    const int g = lane >> 2, t = lane & 3;

    const bool aOk = (m0 + row) < Mrows;
    const __nv_bfloat16* Ap_h = Ahi + (size_t)(m0 + row) * lda + colh;
    const __nv_bfloat16* Ap_l = Alo + (size_t)(m0 + row) * lda + colh;
    const __nv_bfloat16* Bp_h = Bhi + (size_t)(n0 + row) * ldb + colh;
    const __nv_bfloat16* Bp_l = Blo + (size_t)(n0 + row) * ldb + colh;

    const int nkt = K >> 4;
    const uint4 z4 = make_uint4(0u, 0u, 0u, 0u);
    uint4 rah = aOk ? *(const uint4*)Ap_h : z4;
    uint4 ral = aOk ? *(const uint4*)Ap_l : z4;
    uint4 rbh = *(const uint4*)Bp_h;
    uint4 rbl = *(const uint4*)Bp_l;

    for (int kt = 0; kt < nkt; kt++) {
        *(uint4*)&sAh[row * LDK + colh] = rah;
        *(uint4*)&sAl[row * LDK + colh] = ral;
        *(uint4*)&sBh[row * LDK + colh] = rbh;
        *(uint4*)&sBl[row * LDK + colh] = rbl;
        __syncthreads();
        if (kt + 1 < nkt) {
            const int ko = (kt + 1) * 16;
            rah = aOk ? *(const uint4*)(Ap_h + ko) : z4;
            ral = aOk ? *(const uint4*)(Ap_l + ko) : z4;
            rbh = *(const uint4*)(Bp_h + ko);
            rbl = *(const uint4*)(Bp_l + ko);
        }
        // B fragments (k = 2t / 2t+8, n = g)
        uint32_t bh[4][2], bl[4][2];
#pragma unroll
        for (int nt = 0; nt < 4; nt++) {
            int nb = (wn + nt * 8 + g) * LDK + 2 * t;
            bh[nt][0] = *(const uint32_t*)&sBh[nb];
            bh[nt][1] = *(const uint32_t*)&sBh[nb + 8];
            bl[nt][0] = *(const uint32_t*)&sBl[nb];
            bl[nt][1] = *(const uint32_t*)&sBl[nb + 8];
        }
#pragma unroll
        for (int mt = 0; mt < 4; mt++) {
            int mb = (wm + mt * 16 + g) * LDK + 2 * t;
            uint32_t ah0 = *(const uint32_t*)&sAh[mb];
            uint32_t ah1 = *(const uint32_t*)&sAh[mb + 8 * LDK];
            uint32_t ah2 = *(const uint32_t*)&sAh[mb + 8];
            uint32_t ah3 = *(const uint32_t*)&sAh[mb + 8 * LDK + 8];
            uint32_t al0 = *(const uint32_t*)&sAl[mb];
            uint32_t al1 = *(const uint32_t*)&sAl[mb + 8 * LDK];
            uint32_t al2 = *(const uint32_t*)&sAl[mb + 8];
            uint32_t al3 = *(const uint32_t*)&sAl[mb + 8 * LDK + 8];
#pragma unroll
            for (int nt = 0; nt < 4; nt++) {
                mma_bf16_acc(cacc[mt][nt], ah0, ah1, ah2, ah3, bh[nt][0], bh[nt][1]);
                mma_bf16_acc(cacc[mt][nt], ah0, ah1, ah2, ah3, bl[nt][0], bl[nt][1]);
                mma_bf16_acc(cacc[mt][nt], al0, al1, al2, al3, bh[nt][0], bh[nt][1]);
            }
        }
        __syncthreads();
    }
}

// ---------------- kernel 1: fused projections q/k/v/skip/p ----------------
__global__ void __launch_bounds__(256) mma_proj(
    const float* __restrict__ bq, const float* __restrict__ bk,
    const float* __restrict__ bv, const float* __restrict__ bs,
    float* __restrict__ out)
{
    float cacc[4][4][4] = {};
    const int j = blockIdx.x;
    const int m0 = blockIdx.y * 128;
    mma_mainloop(g_xhi, g_xlo, DCH, m0, N_NODES,
                 g_whi, g_wlo, DCH, j * 128, DCH, cacc);

    const int lane = threadIdx.x & 31, wid = threadIdx.x >> 5;
    const int wm = (wid & 1) * 64, wn = (wid >> 1) * 32;
    const int g = lane >> 2, t = lane & 3;

    float* dst; const float* bvec; int col0, ldc;
    if (j < 16) {
        int seg = j >> 2;
        dst = (seg == 0) ? g_q : (seg == 1) ? g_k : (seg == 2) ? g_v : out;
        bvec = (seg == 0) ? bq : (seg == 1) ? bk : (seg == 2) ? bv : bs;
        col0 = (j & 3) * 128; ldc = DCH;
    } else {
        dst = g_p; bvec = g_pbias;
        col0 = (j - 16) * 128; ldc = HEADS * FDIM;
    }
#pragma unroll
    for (int mt = 0; mt < 4; mt++) {
#pragma unroll
        for (int nt = 0; nt < 4; nt++) {
            int gc = col0 + wn + nt * 8 + 2 * t;
            float b0v = bvec[gc], b1v = bvec[gc + 1];
            int r0 = m0 + wm + mt * 16 + g;
            if (r0 < N_NODES) {
                float2 v = make_float2(cacc[mt][nt][0] + b0v, cacc[mt][nt][1] + b1v);
                *(float2*)&dst[(size_t)r0 * ldc + gc] = v;
            }
            int r1 = r0 + 8;
            if (r1 < N_NODES) {
                float2 v = make_float2(cacc[mt][nt][2] + b0v, cacc[mt][nt][3] + b1v);
                *(float2*)&dst[(size_t)r1 * ldc + gc] = v;
            }
        }
    }
}

// ---------------- kernel 2: out += G @ We (per head) ----------------
__global__ void __launch_bounds__(256) mma_out(float* __restrict__ out)
{
    float cacc[4][4][4] = {};
    const int j = blockIdx.x;
    const int h = j >> 1, jt = j & 1;
    const int m0 = blockIdx.y * 128;
    mma_mainloop(g_ghi + h * FDIM, g_glo + h * FDIM, HEADS * FDIM, m0, N_NODES,
                 g_wekthi + (size_t)h * C_HEAD * FDIM,
                 g_wektlo + (size_t)h * C_HEAD * FDIM,
                 FDIM, jt * 128, FDIM, cacc);

    const int lane = threadIdx.x & 31, wid = threadIdx.x >> 5;
    const int wm = (wid & 1) * 64, wn = (wid >> 1) * 32;
    const int g = lane >> 2, t = lane & 3;
    const int col0 = h * C_HEAD + jt * 128;

#pragma unroll
    for (int mt = 0; mt < 4; mt++) {
#pragma unroll
        for (int nt = 0; nt < 4; nt++) {
            int gc = col0 + wn + nt * 8 + 2 * t;
            int r0 = m0 + wm + mt * 16 + g;
            if (r0 < N_NODES) {
                float2* op = (float2*)&out[(size_t)r0 * DCH + gc];
                float2 v = *op;
                v.x += cacc[mt][nt][0]; v.y += cacc[mt][nt][1];
                *op = v;
            }
            int r1 = r0 + 8;
            if (r1 < N_NODES) {
                float2* op = (float2*)&out[(size_t)r1 * DCH + gc];
                float2 v = *op;
                v.x += cacc[mt][nt][2]; v.y += cacc[mt][nt][3];
                *op = v;
            }
        }
    }
}

// ---------------- fp32 GEMM tile (M = Wq @ WeT, writes split-bf16 weights) ------
__device__ __forceinline__ void gemm_tile_split(
    const float* __restrict__ A, int lda,
    const float* __restrict__ B, int ldb,
    int K, int bm, int bn,
    __nv_bfloat16* whi, __nv_bfloat16* wlo, int wrow0,
    float As[2][16][136], float Bs[2][16][128])
{
    const int tid = threadIdx.x;
    const int tx = tid & 15, ty = tid >> 4;
    const int aRow = tid >> 2;
    const int aCol = (tid & 3) * 4;
    const int bRow = tid >> 4;
    const int bCol = (tid & 15) * 4;

    const float* Ap0 = A + (size_t)(bm + aRow) * lda + aCol;
    const float* Ap1 = A + (size_t)(bm + aRow + 64) * lda + aCol;
    const float* Bp0 = B + (size_t)bRow * ldb + bn + bCol;
    const float* Bp1 = Bp0 + 64;
    const int nkt = K >> 4;

    float4 a0r = *(const float4*)Ap0;
    float4 a1r = *(const float4*)Ap1;
    float4 b0r = *(const float4*)Bp0;
    float4 b1r = *(const float4*)Bp1;

    As[0][aCol + 0][aRow] = a0r.x; As[0][aCol + 1][aRow] = a0r.y;
    As[0][aCol + 2][aRow] = a0r.z; As[0][aCol + 3][aRow] = a0r.w;
    As[0][aCol + 0][aRow + 64] = a1r.x; As[0][aCol + 1][aRow + 64] = a1r.y;
    As[0][aCol + 2][aRow + 64] = a1r.z; As[0][aCol + 3][aRow + 64] = a1r.w;
    *(float4*)&Bs[0][bRow][bCol] = b0r;
    *(float4*)&Bs[0][bRow][bCol + 64] = b1r;
    __syncthreads();

    float acc[8][8];
#pragma unroll
    for (int i = 0; i < 8; i++)
#pragma unroll
        for (int jj = 0; jj < 8; jj++) acc[i][jj] = 0.f;

    for (int kt = 0; kt < nkt; kt++) {
        const int s = kt & 1;
        if (kt + 1 < nkt) {
            const int ko = (kt + 1) * 16;
            a0r = *(const float4*)(Ap0 + ko);
            a1r = *(const float4*)(Ap1 + ko);
            b0r = *(const float4*)(Bp0 + (size_t)ko * ldb);
            b1r = *(const float4*)(Bp1 + (size_t)ko * ldb);
        }
#pragma unroll
        for (int kk = 0; kk < 16; kk++) {
            float4 av0 = *(const float4*)&As[s][kk][ty * 8];
            float4 av1 = *(const float4*)&As[s][kk][ty * 8 + 4];
            float4 bv0 = *(const float4*)&Bs[s][kk][tx * 4];
            float4 bv1 = *(const float4*)&Bs[s][kk][tx * 4 + 64];
            float ar[8] = {av0.x, av0.y, av0.z, av0.w, av1.x, av1.y, av1.z, av1.w};
            float br[8] = {bv0.x, bv0.y, bv0.z, bv0.w, bv1.x, bv1.y, bv1.z, bv1.w};
#pragma unroll
            for (int i = 0; i < 8; i++)
#pragma unroll
                for (int jj = 0; jj < 8; jj++) acc[i][jj] += ar[i] * br[jj];
        }
        if (kt + 1 < nkt) {
            __syncthreads();
            const int s1 = s ^ 1;
            As[s1][aCol + 0][aRow] = a0r.x; As[s1][aCol + 1][aRow] = a0r.y;
            As[s1][aCol + 2][aRow] = a0r.z; As[s1][aCol + 3][aRow] = a0r.w;
            As[s1][aCol + 0][aRow + 64] = a1r.x; As[s1][aCol + 1][aRow + 64] = a1r.y;
            As[s1][aCol + 2][aRow + 64] = a1r.z; As[s1][aCol + 3][aRow + 64] = a1r.w;
            *(float4*)&Bs[s1][bRow][bCol] = b0r;
            *(float4*)&Bs[s1][bRow][bCol + 64] = b1r;
            __syncthreads();
        }
    }

#pragma unroll
    for (int i = 0; i < 8; i++) {
        int kk = bm + ty * 8 + i;
#pragma unroll
        for (int jj = 0; jj < 8; jj++) {
            int f = bn + ((jj < 4) ? (tx * 4 + jj) : (64 + tx * 4 + jj - 4));
            int n = wrow0 + f;
            float v = acc[i][jj];
            __nv_bfloat16 h = __float2bfloat16(v);
            whi[(size_t)n * DCH + kk] = h;
            wlo[(size_t)n * DCH + kk] = __float2bfloat16(v - __bfloat162float(h));
        }
    }
}

__global__ void __launch_bounds__(256) gemm_m_kernel(const float* __restrict__ Wq) {
    __shared__ __align__(16) float As[2][16][136];
    __shared__ __align__(16) float Bs[2][16][128];
    int h = blockIdx.z;
    gemm_tile_split(Wq + h * C_HEAD, DCH,
                    g_WeT + (size_t)h * C_HEAD * FDIM, FDIM,
                    C_HEAD, blockIdx.y * 128, blockIdx.x * 128,
                    g_whi, g_wlo, 4 * DCH + h * FDIM, As, Bs);
}

// ---------------- prep: conv x, conv W (qkvs part), conv WeKT, pbias ----------------
#define PB_X  20000
#define PB_W  4096
#define PB_WE 768
#define PB_PB 3
__global__ void misc_prep(const float* __restrict__ x, const float* __restrict__ We,
                          const float* __restrict__ bq,
                          const float* __restrict__ Wq, const float* __restrict__ Wk,
                          const float* __restrict__ Wv, const float* __restrict__ Ws)
{
    int b = blockIdx.x, t = threadIdx.x;
    if (b < PB_X) {
        int i = b * 256 + t;
        float v = x[i];
        __nv_bfloat16 h = __float2bfloat16(v);
        g_xhi[i] = h;
        g_xlo[i] = __float2bfloat16(v - __bfloat162float(h));
    } else if (b < PB_X + PB_W) {
        int idx = (b - PB_X) * 256 + t;
        int k = idx >> 11, n = idx & 2047;
        int seg = n >> 9, cc = n & 511;
        const float* W = (seg == 0) ? Wq : (seg == 1) ? Wk : (seg == 2) ? Wv : Ws;
        float v = W[(size_t)k * DCH + cc];
        __nv_bfloat16 h = __float2bfloat16(v);
        g_whi[(size_t)n * DCH + k] = h;
        g_wlo[(size_t)n * DCH + k] = __float2bfloat16(v - __bfloat162float(h));
    } else if (b < PB_X + PB_W + PB_WE) {
        int idx = (b - PB_X - PB_W) * 256 + t;   // [h][n][k] with k fastest
        int h = idx / (C_HEAD * FDIM);
        int r = idx - h * (C_HEAD * FDIM);
        int n = r / FDIM, k = r - n * FDIM;
        float v = We[(size_t)k * DCH + h * C_HEAD + n];
        __nv_bfloat16 bh = __float2bfloat16(v);
        g_wekthi[idx] = bh;
        g_wektlo[idx] = __float2bfloat16(v - __bfloat162float(bh));
    } else {
        int i = (b - PB_X - PB_W - PB_WE) * 256 + t;
        if (i < HEADS * FDIM) {
            int h = i / FDIM, f = i - h * FDIM;
            float s = 0.f;
            for (int c = 0; c < C_HEAD; c++)
                s += bq[h * C_HEAD + c] * We[(size_t)f * DCH + h * C_HEAD + c];
            g_pbias[i] = s;
        }
    }
}

// ---------------- We transpose ----------------
__global__ void transpose_we_kernel(const float* __restrict__ We) {
    int i = blockIdx.x * 256 + threadIdx.x;
    if (i < HEADS * C_HEAD * FDIM) {
        int h = i / (C_HEAD * FDIM);
        int r = i % (C_HEAD * FDIM);
        int c = r / FDIM;
        int f = r % FDIM;
        g_WeT[i] = We[(size_t)f * DCH + h * C_HEAD + c];
    }
}

// ---------------- CSR build ----------------
__global__ void zero_deg_kernel() {
    int i = blockIdx.x * 256 + threadIdx.x;
    if (i < N_NODES) g_deg[i] = 0;
}
__global__ void count_deg_kernel(const int* __restrict__ ei) {
    int i = blockIdx.x * 256 + threadIdx.x;
    if (i < E_EDGES) atomicAdd(&g_deg[ei[E_EDGES + i]], 1);
}
__global__ void __launch_bounds__(1024) scan_kernel() {
    __shared__ int part[1024];
    int tid = threadIdx.x;
    int base = tid * 10;
    int local[10];
    int s = 0;
#pragma unroll
    for (int j = 0; j < 10; j++) {
        int idx = base + j;
        int d = (idx < N_NODES) ? g_deg[idx] : 0;
        local[j] = d;
        s += d;
    }
    part[tid] = s;
    __syncthreads();
    for (int off = 1; off < 1024; off <<= 1) {
        int v = part[tid];
        int add = (tid >= off) ? part[tid - off] : 0;
        __syncthreads();
        part[tid] = v + add;
        __syncthreads();
    }
    int run = (tid > 0) ? part[tid - 1] : 0;
#pragma unroll
    for (int j = 0; j < 10; j++) {
        int idx = base + j;
        if (idx < N_NODES) {
            g_off[idx] = run;
            run += local[j];
            g_cur[idx] = 0;
        }
    }
    if (tid == 1023) g_off[N_NODES] = part[1023];
}
__global__ void scatter_perm_kernel(const int* __restrict__ ei) {
    int i = blockIdx.x * 256 + threadIdx.x;
    if (i < E_EDGES) {
        int d = ei[E_EDGES + i];
        int p = g_off[d] + atomicAdd(&g_cur[d], 1);
        g_perm[p] = i;
    }
}

// ---------------- CSR-grouped edge logits ----------------
__global__ void __launch_bounds__(128) edge_alpha_kernel(
    const int* __restrict__ ei, const float* __restrict__ tfeat,
    const float* __restrict__ msg)
{
    int n = blockIdx.x;
    int beg = g_off[n];
    int deg = g_off[n + 1] - beg;
    if (deg == 0) return;

    __shared__ __align__(16) float sq[DCH];
    __shared__ __align__(16) float sp[HEADS * FDIM];
    int tid = threadIdx.x;
    ((float4*)sq)[tid] = ((const float4*)(g_q + (size_t)n * DCH))[tid];
    const float4* pr4 = (const float4*)(g_p + (size_t)n * (HEADS * FDIM));
#pragma unroll
    for (int i = tid; i < (HEADS * FDIM) / 4; i += 128)
        ((float4*)sp)[i] = pr4[i];
    __syncthreads();

    int wid = tid >> 5, lane = tid & 31;
    for (int i = wid; i < deg; i += 4) {
        int slot = beg + i;
        int e = g_perm[slot];
        int src = ei[e];
        const float4* kr = (const float4*)(g_k + (size_t)src * DCH);
        float a0 = 0.f, a1 = 0.f;
#pragma unroll
        for (int it = 0; it < 2; it++) {
            float4 kv = kr[lane + 32 * it];
            float4 qv = *(const float4*)&sq[(lane + 32 * it) * 4];
            a0 += kv.x * qv.x + kv.y * qv.y + kv.z * qv.z + kv.w * qv.w;
        }
#pragma unroll
        for (int it = 2; it < 4; it++) {
            float4 kv = kr[lane + 32 * it];
            float4 qv = *(const float4*)&sq[(lane + 32 * it) * 4];
            a1 += kv.x * qv.x + kv.y * qv.y + kv.z * qv.z + kv.w * qv.w;
        }
        {
            float4 tv = ((const float4*)(tfeat + (size_t)e * TDIM))[lane];
            float4 p0 = *(const float4*)&sp[lane * 4];
            float4 p1 = *(const float4*)&sp[FDIM + lane * 4];
            a0 += tv.x * p0.x + tv.y * p0.y + tv.z * p0.z + tv.w * p0.w;
            a1 += tv.x * p1.x + tv.y * p1.y + tv.z * p1.z + tv.w * p1.w;
        }
        const float4* mr4 = (const float4*)(msg + (size_t)e * MDIM);
#pragma unroll
        for (int it = 0; it < 2; it++) {
            float4 mv = mr4[lane + 32 * it];
            int f = TDIM + (lane + 32 * it) * 4;
            float4 p0 = *(const float4*)&sp[f];
            float4 p1 = *(const float4*)&sp[FDIM + f];
            a0 += mv.x * p0.x + mv.y * p0.y + mv.z * p0.z + mv.w * p0.w;
            a1 += mv.x * p1.x + mv.y * p1.y + mv.z * p1.z + mv.w * p1.w;
        }
#pragma unroll
        for (int o = 16; o; o >>= 1) {
            a0 += __shfl_xor_sync(0xffffffffu, a0, o);
            a1 += __shfl_xor_sync(0xffffffffu, a1, o);
        }
        if (lane == 0)
            g_alpha2[slot] = make_float2(a0 * 0.0625f, a1 * 0.0625f);
    }
}

// ---------------- per-node softmax + aggregation (writes split-bf16 G) ----------------
__global__ void __launch_bounds__(128) aggregate_kernel(
    const int* __restrict__ ei, const float* __restrict__ tfeat,
    const float* __restrict__ msg, float* __restrict__ out)
{
    int n = blockIdx.x;
    int tid = threadIdx.x;
    int beg = g_off[n], end = g_off[n + 1];
    int deg = end - beg;

    if (deg == 0) {
        __nv_bfloat16 z = __float2bfloat16(0.f);
#pragma unroll
        for (int l = 0; l < 6; l++) {
            size_t gi = (size_t)n * (HEADS * FDIM) + tid * 6 + l;
            g_ghi[gi] = z;
            g_glo[gi] = z;
        }
        return;
    }

    __shared__ float red0[128], red1[128];

    float m0 = -1e30f, m1 = -1e30f;
    for (int i = tid; i < deg; i += 128) {
        float2 a = g_alpha2[beg + i];
        m0 = fmaxf(m0, a.x);
        m1 = fmaxf(m1, a.y);
    }
    red0[tid] = m0; red1[tid] = m1;
    __syncthreads();
    for (int s = 64; s; s >>= 1) {
        if (tid < s) {
            red0[tid] = fmaxf(red0[tid], red0[tid + s]);
            red1[tid] = fmaxf(red1[tid], red1[tid + s]);
        }
        __syncthreads();
    }
    float amax0 = red0[0], amax1 = red1[0];
    __syncthreads();

    float d0 = 0.f, d1 = 0.f;
    for (int i = tid; i < deg; i += 128) {
        float2 a = g_alpha2[beg + i];
        d0 += expf(a.x - amax0);
        d1 += expf(a.y - amax1);
    }
    red0[tid] = d0; red1[tid] = d1;
    __syncthreads();
    for (int s = 64; s; s >>= 1) {
        if (tid < s) {
            red0[tid] += red0[tid + s];
            red1[tid] += red1[tid + s];
        }
        __syncthreads();
    }
    float inv0 = 1.f / (red0[0] + 1e-16f);
    float inv1 = 1.f / (red1[0] + 1e-16f);
    __syncthreads();

    __shared__ int s_eid[128];
    __shared__ int s_src[128];
    __shared__ float s_w0[128], s_w1[128];

    float acc0 = 0.f, acc1 = 0.f, acc2 = 0.f, acc3 = 0.f;
    float gacc[6] = {0.f, 0.f, 0.f, 0.f, 0.f, 0.f};

    int gf[6]; bool gh1[6];
#pragma unroll
    for (int l = 0; l < 6; l++) {
        int idx = tid * 6 + l;
        gh1[l] = (idx >= FDIM);
        gf[l] = gh1[l] ? idx - FDIM : idx;
    }

    for (int base = 0; base < deg; base += 128) {
        int cnt = min(128, deg - base);
        if (tid < cnt) {
            int slot = beg + base + tid;
            int e = g_perm[slot];
            float2 a = g_alpha2[slot];
            s_eid[tid] = e;
            s_src[tid] = ei[e];
            s_w0[tid] = expf(a.x - amax0) * inv0;
            s_w1[tid] = expf(a.y - amax1) * inv1;
        }
        __syncthreads();
        for (int j = 0; j < cnt; j++) {
            int e = s_eid[j];
            int src = s_src[j];
            float w0 = s_w0[j], w1 = s_w1[j];
            float wv = (tid < 64) ? w0 : w1;
            float4 vv = *(const float4*)(g_v + (size_t)src * DCH + tid * 4);
            acc0 += wv * vv.x; acc1 += wv * vv.y; acc2 += wv * vv.z; acc3 += wv * vv.w;
            const float* tr = tfeat + (size_t)e * TDIM;
            const float* mr = msg + (size_t)e * MDIM;
#pragma unroll
            for (int l = 0; l < 6; l++) {
                int f = gf[l];
                float ea = (f < TDIM) ? tr[f] : mr[f - TDIM];
                gacc[l] += (gh1[l] ? w1 : w0) * ea;
            }
        }
        __syncthreads();
    }

    float4* op = (float4*)(out + (size_t)n * DCH + tid * 4);
    float4 o = *op;
    o.x += acc0; o.y += acc1; o.z += acc2; o.w += acc3;
    *op = o;
#pragma unroll
    for (int l = 0; l < 6; l++) {
        size_t gi = (size_t)n * (HEADS * FDIM) + tid * 6 + l;
        float v = gacc[l];
        __nv_bfloat16 h = __float2bfloat16(v);
        g_ghi[gi] = h;
        g_glo[gi] = __float2bfloat16(v - __bfloat162float(h));
    }
}

// ---------------- launch ----------------
extern "C" void kernel_launch(void* const* d_in, const int* in_sizes, int n_in,
                              void* d_out, int out_size)
{
    const float* x     = (const float*)d_in[0];
    const int*   ei    = (const int*)d_in[2];
    const float* tfeat = (const float*)d_in[3];
    const float* msg   = (const float*)d_in[4];
    const float* Wq    = (const float*)d_in[5];
    const float* bq    = (const float*)d_in[6];
    const float* Wk    = (const float*)d_in[7];
    const float* bk    = (const float*)d_in[8];
    const float* Wv    = (const float*)d_in[9];
    const float* bv    = (const float*)d_in[10];
    const float* We    = (const float*)d_in[11];
    const float* Ws    = (const float*)d_in[12];
    const float* bs    = (const float*)d_in[13];
    float* out = (float*)d_out;

    // 1: conversions + pbias
    misc_prep<<<PB_X + PB_W + PB_WE + PB_PB, 256>>>(x, We, bq, Wq, Wk, Wv, Ws);
    // 2: WeT (fp32, for M)
    transpose_we_kernel<<<(HEADS * C_HEAD * FDIM + 255) / 256, 256>>>(We);
    // 3: M_h = Wq_h @ WeT_h, written as split-bf16 into g_whi/g_wlo rows 2048+
    dim3 gm(FDIM / 128, 4, HEADS);
    gemm_m_kernel<<<gm, 256>>>(Wq);
    // 4: tensor-core (mma.sync) projection GEMM  <-- profiled slot
    dim3 gproj(NCAT / 128, (N_NODES + 127) / 128);
    mma_proj<<<gproj, 256>>>(bq, bk, bv, bs, out);
    // 5-8: CSR
    zero_deg_kernel<<<(N_NODES + 255) / 256, 256>>>();
    count_deg_kernel<<<(E_EDGES + 255) / 256, 256>>>(ei);
    scan_kernel<<<1, 1024>>>();
    scatter_perm_kernel<<<(E_EDGES + 255) / 256, 256>>>(ei);
    // 9: edge logits
    edge_alpha_kernel<<<N_NODES, 128>>>(ei, tfeat, msg);
    // 10: softmax + aggregation (writes split G)
    aggregate_kernel<<<N_NODES, 128>>>(ei, tfeat, msg, out);
    // 11: out += G @ We  (mma.sync)
    dim3 gout(2 * HEADS, (N_NODES + 127) / 128);
    mma_out<<<gout, 256>>>(out);
}